// round 14
// baseline (speedup 1.0000x reference)
#include <cuda_runtime.h>
#include <cuda_bf16.h>
#include <cuda_fp16.h>
#include <cstdint>

#define NSEQ   16384
#define BNTOK  65536
#define LC     64
#define NCH    256
#define NTILE  512
#define SASTR  272
#define R1OFF  69632u
#define R2OFF  139264u

__device__ __half g_yh[2][(size_t)BNTOK * 128];
__device__ __nv_bfloat16 g_Wtb[5][2][16384];
__device__ __half g_Wth[2][2][16384];
__device__ float g_biasv[640];

__device__ __half g_z [2u*BNTOK*128];
__device__ __half g_uc[2u*BNTOK*128];
__device__ float g_xdbl[2u*BNTOK*24];
__device__ float g_P [2u*4*NCH*128*8];
__device__ float g_Q [2u*4*NCH*128*8];
__device__ float g_H [2u*4*NCH*128*8];
__device__ float g_segP[65536], g_segQ[65536], g_segH[65536];

__device__ __forceinline__ float sigmoidf_fast(float x) { return 1.0f / (1.0f + __expf(-x)); }
__device__ __forceinline__ float softplusf(float x) { return (x > 15.0f) ? x : __logf(1.0f + __expf(x)); }
__device__ __forceinline__ uint32_t su32(const void* p) { return (uint32_t)__cvta_generic_to_shared(p); }

__device__ __forceinline__ void cpa16(uint32_t s, const void* g) {
    asm volatile("cp.async.cg.shared.global [%0], [%1], 16;" :: "r"(s), "l"(g));
}
#define CP_COMMIT() asm volatile("cp.async.commit_group;")
#define CP_WAIT(n)  asm volatile("cp.async.wait_group %0;" :: "n"(n))

__device__ __forceinline__ void splt(float a, float b, uint32_t& hi, uint32_t& lo) {
    __nv_bfloat162 h, l;
    h.x = __float2bfloat16_rn(a); h.y = __float2bfloat16_rn(b);
    l.x = __float2bfloat16_rn(a - __bfloat162float(h.x));
    l.y = __float2bfloat16_rn(b - __bfloat162float(h.y));
    hi = *(uint32_t*)&h; lo = *(uint32_t*)&l;
}
__device__ __forceinline__ void ldsm4(uint32_t addr, uint32_t r[4]) {
    asm volatile("ldmatrix.sync.aligned.m8n8.x4.shared.b16 {%0,%1,%2,%3}, [%4];"
                 : "=r"(r[0]), "=r"(r[1]), "=r"(r[2]), "=r"(r[3]) : "r"(addr));
}
__device__ __forceinline__ void mma16816(float d[4], const uint32_t a[4], const uint32_t b[2]) {
    asm volatile("mma.sync.aligned.m16n8k16.row.col.f32.bf16.bf16.f32 "
                 "{%0,%1,%2,%3},{%4,%5,%6,%7},{%8,%9},{%0,%1,%2,%3};"
                 : "+f"(d[0]), "+f"(d[1]), "+f"(d[2]), "+f"(d[3])
                 : "r"(a[0]), "r"(a[1]), "r"(a[2]), "r"(a[3]), "r"(b[0]), "r"(b[1]));
}
__device__ __forceinline__ void mma16816h(float d[4], const uint32_t a[4], const uint32_t b[2]) {
    asm volatile("mma.sync.aligned.m16n8k16.row.col.f32.f16.f16.f32 "
                 "{%0,%1,%2,%3},{%4,%5,%6,%7},{%8,%9},{%0,%1,%2,%3};"
                 : "+f"(d[0]), "+f"(d[1]), "+f"(d[2]), "+f"(d[3])
                 : "r"(a[0]), "r"(a[1]), "r"(a[2]), "r"(a[3]), "r"(b[0]), "r"(b[1]));
}

__device__ __forceinline__ void cpa_plane(const void* __restrict__ g, uint32_t s, int tid) {
#pragma unroll
    for (int it = 0; it < 8; ++it) {
        int idx = tid + it * 256;
        int r = idx >> 4, c = idx & 15;
        cpa16(s + (uint32_t)(r * SASTR + c * 16), (const char*)g + idx * 16);
    }
}

// bf16 3-pass hi/lo GEMM
__device__ __forceinline__ void gemm_compute(uint32_t Ab0, uint32_t Bb0, float acc[16][4],
                                             int warp, int lane) {
    int row = lane & 7, g = lane >> 3;
    uint32_t aoff = (uint32_t)((warp * 16 + (g & 1) * 8 + row) * SASTR + (g >> 1) * 16);
    uint32_t boff = (uint32_t)(((g >> 1) * 8 + row) * SASTR + (g & 1) * 16);
#pragma unroll
    for (int pass = 0; pass < 3; ++pass) {
        uint32_t Ab = Ab0 + (pass == 1 ? 34816u : 0u);
        uint32_t Bb = Bb0 + (pass == 2 ? 34816u : 0u);
#pragma unroll
        for (int kk = 0; kk < 8; ++kk) {
            uint32_t k2 = (uint32_t)kk * 32u;
            uint32_t a[4];
            ldsm4(Ab + aoff + k2, a);
#pragma unroll
            for (int nt = 0; nt < 8; ++nt) {
                uint32_t br[4];
                ldsm4(Bb + boff + (uint32_t)(nt * 16 * SASTR) + k2, br);
                mma16816(acc[2 * nt], a, br);
                mma16816(acc[2 * nt + 1], a, br + 2);
            }
        }
    }
}

// f16 2-pass GEMM: A single plane, B = fp16 hi/lo pair
__device__ __forceinline__ void gemm_f16(uint32_t Ab, uint32_t Bb0, float acc[16][4],
                                         int warp, int lane) {
    int row = lane & 7, g = lane >> 3;
    uint32_t aoff = (uint32_t)((warp * 16 + (g & 1) * 8 + row) * SASTR + (g >> 1) * 16);
    uint32_t boff = (uint32_t)(((g >> 1) * 8 + row) * SASTR + (g & 1) * 16);
#pragma unroll
    for (int pass = 0; pass < 2; ++pass) {
        uint32_t Bb = Bb0 + (pass == 1 ? 34816u : 0u);
#pragma unroll
        for (int kk = 0; kk < 8; ++kk) {
            uint32_t k2 = (uint32_t)kk * 32u;
            uint32_t a[4];
            ldsm4(Ab + aoff + k2, a);
#pragma unroll
            for (int nt = 0; nt < 8; ++nt) {
                uint32_t br[4];
                ldsm4(Bb + boff + (uint32_t)(nt * 16 * SASTR) + k2, br);
                mma16816h(acc[2 * nt], a, br);
                mma16816h(acc[2 * nt + 1], a, br + 2);
            }
        }
    }
}

// ---------------- prep_w ----------------
extern "C" __global__ void prep_w_kernel(
    const float* __restrict__ ln0w, const float* __restrict__ ln0b,
    const float* __restrict__ ln1w, const float* __restrict__ ln1b,
    const float* __restrict__ Wx, const float* __restrict__ Wz,
    const float* __restrict__ Wm, const float* __restrict__ bm,
    const float* __restrict__ Wout, const float* __restrict__ bout) {
    int j = blockIdx.x, pl = blockIdx.y, k = threadIdx.x;
    __shared__ float red[128];
    float v = 0.f, bc = 0.f;
    if (pl < 4) {
        int dir = pl >> 1;
        const float* W  = ((pl & 1) ? Wz : Wx) + dir * 16384;
        const float* lw = ((pl & 1) ? ln1w : ln0w) + dir * 128;
        const float* lb = ((pl & 1) ? ln1b : ln0b) + dir * 128;
        float wv = W[k * 128 + j];
        v = lw[k] * wv; bc = lb[k] * wv;
    } else if (pl == 4) {
        float wv = Wout[k * 128 + j];
        v = wv; bc = 0.5f * (bm[k] + bm[128 + k]) * wv;
    } else {
        int i = pl - 5;
        float acc = 0.f;
        for (int t = 0; t < 128; ++t) acc += Wm[i * 16384 + k * 128 + t] * Wout[t * 128 + j];
        v = 0.5f * acc;
    }
    if (pl < 5) {
        __nv_bfloat16 h = __float2bfloat16_rn(v);
        g_Wtb[pl][0][j * 128 + k] = h;
        g_Wtb[pl][1][j * 128 + k] = __float2bfloat16_rn(v - __bfloat162float(h));
        red[k] = bc; __syncthreads();
        if (k == 0) {
            float s = 0.f;
            for (int t = 0; t < 128; ++t) s += red[t];
            if (pl < 4) g_biasv[pl * 128 + j] = s;
            else        g_biasv[512 + j] = s + bout[j];
        }
    } else {
        __half hh = __float2half_rn(v);
        g_Wth[pl - 5][0][j * 128 + k] = hh;
        g_Wth[pl - 5][1][j * 128 + k] = __float2half_rn(v - __half2float(hh));
    }
}

// ---------------- gemm_in ----------------
extern "C" __global__ void __launch_bounds__(256) gemm_in_kernel(
    const float* __restrict__ front, const float* __restrict__ back,
    const float* __restrict__ conv_w, const float* __restrict__ conv_b,
    const float* __restrict__ Wxproj) {
    extern __shared__ unsigned char smu[];
    __shared__ float s_biasu[128], s_biasz[128];
    __shared__ float s_uh[3 * 128];
    __shared__ float s_cw[128 * 4];
    __shared__ float s_cb[128];
    __shared__ float s_sum[2][128], s_sum2[2][128];
    __shared__ float s_mean[128], s_rstd[128];
    __shared__ float s_hx[3][128];
    __shared__ float s_hst[6];
    int tid = threadIdx.x, warp = tid >> 5, lane = tid & 31;
    int T = blockIdx.x, p = blockIdx.y;
    int ucm = p ? 2 : 0, zcm = p ? 1 : 3;
    int udir = p, zdir = 1 - p;
    int g0 = T * 128, b = g0 >> 14, n0 = g0 & (NSEQ - 1);
    const float* src = (p ? back : front) + (size_t)b * 128 * NSEQ + n0;
    uint32_t sb = su32(smu);

#pragma unroll
    for (int it = 0; it < 16; ++it) {
        int idx = tid + it * 256, d = idx >> 5, v = idx & 31;
        cpa16(sb + R1OFF + (uint32_t)(d * 528 + v * 16), src + (size_t)d * NSEQ + v * 4);
    }
    CP_COMMIT();
    cpa_plane(g_Wtb[zcm][0], sb + R2OFF, tid);
    cpa_plane(g_Wtb[zcm][1], sb + R2OFF + 34816u, tid);
    CP_COMMIT();
    if (tid < 128) {
        s_biasu[tid] = g_biasv[ucm * 128 + tid];
        s_biasz[tid] = g_biasv[zcm * 128 + tid];
        *(float4*)(s_cw + tid * 4) = *(const float4*)(conv_w + udir * 512 + tid * 4);
        s_cb[tid] = conv_b[udir * 128 + tid];
    }
    CP_WAIT(1);
    __syncthreads();

    float* xt = (float*)(smu + R1OFF);
    {
        int t = tid & 127, hf = tid >> 7;
        float a = 0.f, q = 0.f;
        for (int d = hf * 64; d < hf * 64 + 64; ++d) {
            float x = xt[d * 132 + t];
            a += x; q += x * x;
        }
        s_sum[hf][t] = a; s_sum2[hf][t] = q;
    }
    __syncthreads();
    if (tid < 128) {
        float m = (s_sum[0][tid] + s_sum[1][tid]) * (1.f / 128.f);
        float q = (s_sum2[0][tid] + s_sum2[1][tid]) * (1.f / 128.f);
        s_mean[tid] = m;
        s_rstd[tid] = rsqrtf(q - m * m + 1e-5f);
    }
    __syncthreads();
#pragma unroll
    for (int it = 0; it < 8; ++it) {
        int u = tid + it * 256;
        int tok = u & 127, kk = (u >> 7) * 8;
        float m = s_mean[tok], r = s_rstd[tok];
        float v[8];
#pragma unroll
        for (int q = 0; q < 8; ++q) v[q] = (xt[(kk + q) * 132 + tok] - m) * r;
        uint32_t hi[4], lo[4];
#pragma unroll
        for (int r2 = 0; r2 < 4; ++r2) splt(v[2 * r2], v[2 * r2 + 1], hi[r2], lo[r2]);
        *(uint4*)(smu + tok * SASTR + kk * 2)         = make_uint4(hi[0], hi[1], hi[2], hi[3]);
        *(uint4*)(smu + 34816 + tok * SASTR + kk * 2) = make_uint4(lo[0], lo[1], lo[2], lo[3]);
    }
    __syncthreads();
    cpa_plane(g_Wtb[ucm][0], sb + R1OFF, tid);
    cpa_plane(g_Wtb[ucm][1], sb + R1OFF + 34816u, tid);
    CP_COMMIT();
    CP_WAIT(1);
    __syncthreads();

    int r0 = warp * 16 + (lane >> 2);
    int cb2 = (lane & 3) * 2;
    float acc[16][4];

#pragma unroll
    for (int n = 0; n < 16; ++n)
#pragma unroll
        for (int q = 0; q < 4; ++q) acc[n][q] = 0.f;
    gemm_compute(sb, sb + R2OFF, acc, warp, lane);
    {
        __half* d0 = g_z + (size_t)zdir * BNTOK * 128 + ((size_t)(T * 128) + r0) * 128;
#pragma unroll
        for (int nt = 0; nt < 16; ++nt) {
            int col = nt * 8 + cb2;
            float b0 = s_biasz[col], b1 = s_biasz[col + 1];
            *(__half2*)(d0 + col)           = __floats2half2_rn(acc[nt][0] + b0, acc[nt][1] + b1);
            *(__half2*)(d0 + 8 * 128 + col) = __floats2half2_rn(acc[nt][2] + b0, acc[nt][3] + b1);
        }
    }
    CP_WAIT(0);
    __syncthreads();

#pragma unroll
    for (int n = 0; n < 16; ++n)
#pragma unroll
        for (int q = 0; q < 4; ++q) acc[n][q] = 0.f;
    gemm_compute(sb, sb + R1OFF, acc, warp, lane);

    __syncthreads();
    float* ut = (float*)(smu + R2OFF);
#pragma unroll
    for (int nt = 0; nt < 16; ++nt) {
        int col = nt * 8 + cb2;
        float b0 = s_biasu[col], b1 = s_biasu[col + 1];
        ut[r0 * 132 + col]           = acc[nt][0] + b0;
        ut[r0 * 132 + col + 1]       = acc[nt][1] + b1;
        ut[(r0 + 8) * 132 + col]     = acc[nt][2] + b0;
        ut[(r0 + 8) * 132 + col + 1] = acc[nt][3] + b1;
    }
    if (T & 127) {
        if (tid < 128) {
            const float* hs = (p ? back : front) + (size_t)b * 128 * NSEQ + (n0 - 3);
            s_hx[0][tid] = hs[(size_t)tid * NSEQ + 0];
            s_hx[1][tid] = hs[(size_t)tid * NSEQ + 1];
            s_hx[2][tid] = hs[(size_t)tid * NSEQ + 2];
        }
        __syncthreads();
        if (tid < 6) {
            int k = tid >> 1, sq = tid & 1;
            float s = 0.f;
            for (int d = 0; d < 128; ++d) {
                float x = s_hx[k][d];
                s += sq ? x * x : x;
            }
            s_hst[tid] = s;
        }
        __syncthreads();
        if (tid < 128) {
#pragma unroll
            for (int k = 0; k < 3; ++k) {
                float m = s_hst[2 * k] * (1.f / 128.f);
                float q = s_hst[2 * k + 1] * (1.f / 128.f);
                float r = rsqrtf(q - m * m + 1e-5f);
                s_hx[k][tid] = (s_hx[k][tid] - m) * r;
            }
        }
        __syncthreads();
        if (tid < 128) {
            int j = tid;
            const __nv_bfloat16* wh = (const __nv_bfloat16*)(smu + R1OFF + j * SASTR);
            const __nv_bfloat16* wl = (const __nv_bfloat16*)(smu + R1OFF + 34816 + j * SASTR);
            float a0 = s_biasu[j], a1 = s_biasu[j], a2 = s_biasu[j];
            for (int k = 0; k < 128; ++k) {
                float w = __bfloat162float(wh[k]) + __bfloat162float(wl[k]);
                a0 += w * s_hx[0][k];
                a1 += w * s_hx[1][k];
                a2 += w * s_hx[2][k];
            }
            s_uh[j] = a0; s_uh[128 + j] = a1; s_uh[256 + j] = a2;
        }
    } else {
        if (tid < 128) { s_uh[tid] = 0.f; s_uh[128 + tid] = 0.f; s_uh[256 + tid] = 0.f; }
    }
    __syncthreads();
    float* uct = (float*)smu;
    float* wxpd = (float*)(smu + R1OFF);
    __half* ucg = g_uc + (size_t)udir * BNTOK * 128 + (size_t)T * 128 * 128;
#pragma unroll
    for (int it = 0; it < 12; ++it)
        wxpd[tid + it * 256] = Wxproj[udir * 3072 + tid + it * 256];
#pragma unroll
    for (int it = 0; it < 16; ++it) {
        int idx = tid + it * 256;
        int t = idx >> 5, dq = (idx & 31) * 4;
        float4 r3, r2, r1, r0v;
        r0v = *(float4*)(ut + t * 132 + dq);
        if (t >= 3) {
            r3 = *(float4*)(ut + (t - 3) * 132 + dq);
            r2 = *(float4*)(ut + (t - 2) * 132 + dq);
            r1 = *(float4*)(ut + (t - 1) * 132 + dq);
        } else {
            r3 = (t < 3) ? *(float4*)(s_uh + t * 128 + dq)       : *(float4*)(ut + (t - 3) * 132 + dq);
            r2 = (t < 2) ? *(float4*)(s_uh + (t + 1) * 128 + dq) : *(float4*)(ut + (t - 2) * 132 + dq);
            r1 = (t < 1) ? *(float4*)(s_uh + (t + 2) * 128 + dq) : *(float4*)(ut + (t - 1) * 132 + dq);
        }
        float4 o;
        float* w;
        w = s_cw + (dq + 0) * 4;
        o.x = s_cb[dq + 0] + w[0] * r3.x + w[1] * r2.x + w[2] * r1.x + w[3] * r0v.x;
        w = s_cw + (dq + 1) * 4;
        o.y = s_cb[dq + 1] + w[0] * r3.y + w[1] * r2.y + w[2] * r1.y + w[3] * r0v.y;
        w = s_cw + (dq + 2) * 4;
        o.z = s_cb[dq + 2] + w[0] * r3.z + w[1] * r2.z + w[2] * r1.z + w[3] * r0v.z;
        w = s_cw + (dq + 3) * 4;
        o.w = s_cb[dq + 3] + w[0] * r3.w + w[1] * r2.w + w[2] * r1.w + w[3] * r0v.w;
        o.x *= sigmoidf_fast(o.x); o.y *= sigmoidf_fast(o.y);
        o.z *= sigmoidf_fast(o.z); o.w *= sigmoidf_fast(o.w);
        *(float4*)(uct + t * 132 + dq) = o;
        __half2 h01 = __floats2half2_rn(o.x, o.y);
        __half2 h23 = __floats2half2_rn(o.z, o.w);
        *(uint2*)(ucg + (size_t)t * 128 + dq) = make_uint2(*(uint32_t*)&h01, *(uint32_t*)&h23);
    }
    __syncthreads();
    {
        int tok = tid >> 1, hf = tid & 1;
        float a2[12];
#pragma unroll
        for (int q = 0; q < 12; ++q) a2[q] = 0.f;
        const float* ur = uct + tok * 132;
        const float* wp = wxpd + hf * 12;
        for (int d = 0; d < 128; ++d) {
            float uv = ur[d];
#pragma unroll
            for (int q = 0; q < 12; ++q) a2[q] += uv * wp[d * 24 + q];
        }
        float* xo = g_xdbl + ((size_t)udir * BNTOK + T * 128 + tok) * 24 + hf * 12;
        *(float4*)(xo + 0) = make_float4(a2[0], a2[1], a2[2], a2[3]);
        *(float4*)(xo + 4) = make_float4(a2[4], a2[5], a2[6], a2[7]);
        *(float4*)(xo + 8) = make_float4(a2[8], a2[9], a2[10], a2[11]);
    }
}

// ---------------- scan_a ----------------
extern "C" __global__ void __launch_bounds__(128) scan_a_kernel(
    const float* __restrict__ A_log, const float* __restrict__ Wdt,
    const float* __restrict__ bdt) {
    __shared__ float xds[LC * 24];
    __shared__ float wdts[8 * 128], bdts[128];
    int bx = blockIdx.x, c = bx & (NCH - 1), b = (bx >> 8) & 3, i = bx >> 10, d = threadIdx.x;
    float a[8];
#pragma unroll
    for (int s = 0; s < 8; ++s) a[s] = -__expf(A_log[i * 1024 + d * 8 + s]);
    bool st = true;
#pragma unroll
    for (int s = 1; s < 8; ++s)
        st = st && (fabsf(a[s] - (float)(s + 1) * a[0]) <= 1e-4f * fabsf(a[s]));
    size_t g0 = (size_t)i * BNTOK + b * NSEQ + c * LC;
#pragma unroll
    for (int k = 0; k < 12; ++k) xds[d + k * 128] = g_xdbl[g0 * 24 + d + k * 128];
#pragma unroll
    for (int k = 0; k < 8; ++k) wdts[d + k * 128] = Wdt[i * 1024 + d + k * 128];
    bdts[d] = bdt[i * 128 + d];
    __syncthreads();
    float P[8], h[8];
#pragma unroll
    for (int s = 0; s < 8; ++s) { P[s] = 1.f; h[s] = 0.f; }
    const __half* ucp = g_uc + g0 * 128 + d;
    if (st) {
        float a0 = a[0];
#pragma unroll 2
        for (int t = 0; t < LC; ++t) {
            float dtacc = bdts[d];
#pragma unroll
            for (int r = 0; r < 8; ++r) dtacc += xds[t * 24 + r] * wdts[r * 128 + d];
            float dtv = softplusf(dtacc);
            float du = dtv * __half2float(ucp[t * 128]);
            float e1 = __expf(dtv * a0);
            float dA = e1;
#pragma unroll
            for (int s = 0; s < 8; ++s) {
                P[s] *= dA;
                h[s] = dA * h[s] + du * xds[t * 24 + 8 + s];
                dA *= e1;
            }
        }
    } else {
#pragma unroll 2
        for (int t = 0; t < LC; ++t) {
            float dtacc = bdts[d];
#pragma unroll
            for (int r = 0; r < 8; ++r) dtacc += xds[t * 24 + r] * wdts[r * 128 + d];
            float dtv = softplusf(dtacc);
            float du = dtv * __half2float(ucp[t * 128]);
#pragma unroll
            for (int s = 0; s < 8; ++s) {
                float dA = __expf(dtv * a[s]);
                P[s] *= dA;
                h[s] = dA * h[s] + du * xds[t * 24 + 8 + s];
            }
        }
    }
    size_t o = ((size_t)((i * 4 + b) * NCH + c)) * 1024 + d * 8;
    *(float4*)(g_P + o) = make_float4(P[0], P[1], P[2], P[3]);
    *(float4*)(g_P + o + 4) = make_float4(P[4], P[5], P[6], P[7]);
    *(float4*)(g_Q + o) = make_float4(h[0], h[1], h[2], h[3]);
    *(float4*)(g_Q + o + 4) = make_float4(h[4], h[5], h[6], h[7]);
}

// ---------------- scan_b (tree) ----------------
extern "C" __global__ void __launch_bounds__(256) scan_b1_kernel() {
    int gid = blockIdx.x * 256 + threadIdx.x;
    int seg = gid >> 13, rem = gid & 8191;
    size_t base = (size_t)(rem >> 10) * NCH * 1024 + (size_t)(seg * 32) * 1024 + (rem & 1023);
    float Pa = 1.f, Qa = 0.f;
    for (int k0 = 0; k0 < 32; k0 += 8) {
        float P8[8], Q8[8];
#pragma unroll
        for (int k = 0; k < 8; ++k) {
            size_t o = base + (size_t)(k0 + k) * 1024;
            P8[k] = g_P[o]; Q8[k] = g_Q[o];
        }
#pragma unroll
        for (int k = 0; k < 8; ++k) { Qa = P8[k] * Qa + Q8[k]; Pa *= P8[k]; }
    }
    g_segP[seg * 8192 + rem] = Pa;
    g_segQ[seg * 8192 + rem] = Qa;
}
extern "C" __global__ void __launch_bounds__(256) scan_b2_kernel() {
    int gid = blockIdx.x * 256 + threadIdx.x;
    float Ps[8], Qs[8];
#pragma unroll
    for (int s = 0; s < 8; ++s) { Ps[s] = g_segP[s * 8192 + gid]; Qs[s] = g_segQ[s * 8192 + gid]; }
    float h = 0.f;
#pragma unroll
    for (int s = 0; s < 8; ++s) {
        g_segH[s * 8192 + gid] = h;
        h = Ps[s] * h + Qs[s];
    }
}
extern "C" __global__ void __launch_bounds__(256) scan_b3_kernel() {
    int gid = blockIdx.x * 256 + threadIdx.x;
    int seg = gid >> 13, rem = gid & 8191;
    size_t base = (size_t)(rem >> 10) * NCH * 1024 + (size_t)(seg * 32) * 1024 + (rem & 1023);
    float h = g_segH[seg * 8192 + rem];
    for (int k0 = 0; k0 < 32; k0 += 8) {
        float P8[8], Q8[8];
#pragma unroll
        for (int k = 0; k < 8; ++k) {
            size_t o = base + (size_t)(k0 + k) * 1024;
            P8[k] = g_P[o]; Q8[k] = g_Q[o];
        }
#pragma unroll
        for (int k = 0; k < 8; ++k) {
            size_t o = base + (size_t)(k0 + k) * 1024;
            g_H[o] = h;
            h = P8[k] * h + Q8[k];
        }
    }
}

// ---------------- scan_c ----------------
extern "C" __global__ void __launch_bounds__(128) scan_c_kernel(
    const float* __restrict__ A_log, const float* __restrict__ Dp,
    const float* __restrict__ Wdt, const float* __restrict__ bdt) {
    __shared__ float xds[LC * 24];
    __shared__ float wdts[8 * 128], bdts[128];
    __shared__ float ys_s[LC * 131];
    int bx = blockIdx.x, c = bx & (NCH - 1), b = (bx >> 8) & 3, i = bx >> 10, d = threadIdx.x;
    float a[8];
#pragma unroll
    for (int s = 0; s < 8; ++s) a[s] = -__expf(A_log[i * 1024 + d * 8 + s]);
    bool st = true;
#pragma unroll
    for (int s = 1; s < 8; ++s)
        st = st && (fabsf(a[s] - (float)(s + 1) * a[0]) <= 1e-4f * fabsf(a[s]));
    float dp = Dp[i * 128 + d];
    size_t g0 = (size_t)i * BNTOK + b * NSEQ + c * LC;
#pragma unroll
    for (int k = 0; k < 12; ++k) xds[d + k * 128] = g_xdbl[g0 * 24 + d + k * 128];
#pragma unroll
    for (int k = 0; k < 8; ++k) wdts[d + k * 128] = Wdt[i * 1024 + d + k * 128];
    bdts[d] = bdt[i * 128 + d];
    __syncthreads();
    size_t o = ((size_t)((i * 4 + b) * NCH + c)) * 1024 + d * 8;
    float h[8];
    float4 h0 = *(const float4*)(g_H + o), h1 = *(const float4*)(g_H + o + 4);
    h[0] = h0.x; h[1] = h0.y; h[2] = h0.z; h[3] = h0.w;
    h[4] = h1.x; h[5] = h1.y; h[6] = h1.z; h[7] = h1.w;
    const __half* ucp = g_uc + g0 * 128 + d;
    const __half* zp  = g_z  + g0 * 128 + d;
    if (st) {
        float a0 = a[0];
#pragma unroll 2
        for (int t = 0; t < LC; ++t) {
            float dtacc = bdts[d];
#pragma unroll
            for (int r = 0; r < 8; ++r) dtacc += xds[t * 24 + r] * wdts[r * 128 + d];
            float dtv = softplusf(dtacc);
            float ucv = __half2float(ucp[t * 128]), zv = __half2float(zp[t * 128]);
            float du = dtv * ucv, y = 0.f;
            float e1 = __expf(dtv * a0);
            float dA = e1;
#pragma unroll
            for (int s = 0; s < 8; ++s) {
                h[s] = dA * h[s] + du * xds[t * 24 + 8 + s];
                y += h[s] * xds[t * 24 + 16 + s];
                dA *= e1;
            }
            ys_s[t * 131 + d] = (y + dp * ucv) * (zv * sigmoidf_fast(zv));
        }
    } else {
#pragma unroll 2
        for (int t = 0; t < LC; ++t) {
            float dtacc = bdts[d];
#pragma unroll
            for (int r = 0; r < 8; ++r) dtacc += xds[t * 24 + r] * wdts[r * 128 + d];
            float dtv = softplusf(dtacc);
            float ucv = __half2float(ucp[t * 128]), zv = __half2float(zp[t * 128]);
            float du = dtv * ucv, y = 0.f;
#pragma unroll
            for (int s = 0; s < 8; ++s) {
                float dA = __expf(dtv * a[s]);
                h[s] = dA * h[s] + du * xds[t * 24 + 8 + s];
                y += h[s] * xds[t * 24 + 16 + s];
            }
            ys_s[t * 131 + d] = (y + dp * ucv) * (zv * sigmoidf_fast(zv));
        }
    }
    __syncthreads();
    int tile = (b * NSEQ + c * LC) >> 7;
    int half = (c & 1) * 64;
#pragma unroll
    for (int it = 0; it < 8; ++it) {
        int u = d + it * 128;
        int tt = u & 63, kk = (u >> 6) * 8;
        __half2 p0 = __floats2half2_rn(ys_s[tt * 131 + kk + 0], ys_s[tt * 131 + kk + 1]);
        __half2 p1 = __floats2half2_rn(ys_s[tt * 131 + kk + 2], ys_s[tt * 131 + kk + 3]);
        __half2 p2 = __floats2half2_rn(ys_s[tt * 131 + kk + 4], ys_s[tt * 131 + kk + 5]);
        __half2 p3 = __floats2half2_rn(ys_s[tt * 131 + kk + 6], ys_s[tt * 131 + kk + 7]);
        size_t off = ((size_t)(tile * 128 + half + tt)) * 128 + kk;
        *(uint4*)(&g_yh[i][off]) = make_uint4(*(uint32_t*)&p0, *(uint32_t*)&p1,
                                             *(uint32_t*)&p2, *(uint32_t*)&p3);
    }
}

// ---------------- gemm_out: m bf16 3-pass + 2 y fp16 2-pass phases ----------------
extern "C" __global__ void __launch_bounds__(256) gemm_out_kernel(
    float* __restrict__ outp, const float* __restrict__ front,
    const float* __restrict__ back) {
    extern __shared__ unsigned char smu[];
    int tid = threadIdx.x, warp = tid >> 5, lane = tid & 31;
    int T = blockIdx.x, g0 = T * 128, b = g0 >> 14, n0 = g0 & (NSEQ - 1);
    uint32_t sb = su32(smu);
    float acc[16][4];
#pragma unroll
    for (int n = 0; n < 16; ++n)
#pragma unroll
        for (int q = 0; q < 4; ++q) acc[n][q] = 0.f;
    size_t abase = (size_t)T * 128 * 128;

    // G1: y0 fp16 -> R2 (streams during m build)
    cpa_plane(&g_yh[0][abase], sb + R2OFF, tid);
    CP_COMMIT();

    // build m-tile -> R0 (bf16 hi/lo), R1 = fp32 staging
    for (int r = 0; r < 2; ++r) {
        float* fm = (float*)(smu + R1OFF);
        float* bm = fm + 128 * 68;
        const float* fp = front + (size_t)b * 128 * NSEQ + n0 + r * 64;
        const float* bp = back  + (size_t)b * 128 * NSEQ + n0 + r * 64;
#pragma unroll
        for (int it = 0; it < 8; ++it) {
            int idx = tid + it * 256, d = idx >> 4, v = idx & 15;
            *(float4*)(fm + d * 68 + v * 4) = *(const float4*)(fp + (size_t)d * NSEQ + v * 4);
            *(float4*)(bm + d * 68 + v * 4) = *(const float4*)(bp + (size_t)d * NSEQ + v * 4);
        }
        __syncthreads();
#pragma unroll
        for (int it = 0; it < 4; ++it) {
            int u = tid + it * 256;
            int tok = u & 63, kk = (u >> 6) * 8;
            float v[8];
#pragma unroll
            for (int q = 0; q < 8; ++q)
                v[q] = 0.5f * (fm[(kk + q) * 68 + tok] + bm[(kk + q) * 68 + tok]);
            uint32_t hi[4], lo[4];
#pragma unroll
            for (int r2 = 0; r2 < 4; ++r2) splt(v[2 * r2], v[2 * r2 + 1], hi[r2], lo[r2]);
            *(uint4*)(smu + (r * 64 + tok) * SASTR + kk * 2)         = make_uint4(hi[0], hi[1], hi[2], hi[3]);
            *(uint4*)(smu + 34816 + (r * 64 + tok) * SASTR + kk * 2) = make_uint4(lo[0], lo[1], lo[2], lo[3]);
        }
        __syncthreads();
    }
    cpa_plane(g_Wtb[4][0], sb + R1OFF, tid);
    cpa_plane(g_Wtb[4][1], sb + R1OFF + 34816u, tid);
    CP_COMMIT();
    CP_WAIT(0);
    __syncthreads();
    gemm_compute(sb, sb + R1OFF, acc, warp, lane);   // m @ Wout (bf16 3-pass)
    __syncthreads();

    // G: Weff0 fp16 pair -> R1; G: y1 fp16 -> R0
    cpa_plane(g_Wth[0][0], sb + R1OFF, tid);
    cpa_plane(g_Wth[0][1], sb + R1OFF + 34816u, tid);
    CP_COMMIT();
    cpa_plane(&g_yh[1][abase], sb, tid);
    CP_COMMIT();
    CP_WAIT(1);
    __syncthreads();
    gemm_f16(sb + R2OFF, sb + R1OFF, acc, warp, lane);   // y0 @ Weff0 (fp16 2-pass)
    __syncthreads();

    cpa_plane(g_Wth[1][0], sb + R1OFF, tid);
    cpa_plane(g_Wth[1][1], sb + R1OFF + 34816u, tid);
    CP_COMMIT();
    CP_WAIT(0);
    __syncthreads();
    gemm_f16(sb, sb + R1OFF, acc, warp, lane);           // y1 @ Weff1

    __syncthreads();
    float* res = (float*)smu;
    int r0 = warp * 16 + (lane >> 2);
    int cb = (lane & 3) * 2;
#pragma unroll
    for (int nt = 0; nt < 16; ++nt) {
        int col = nt * 8 + cb;
        res[r0 * 132 + col]           = acc[nt][0];
        res[r0 * 132 + col + 1]       = acc[nt][1];
        res[(r0 + 8) * 132 + col]     = acc[nt][2];
        res[(r0 + 8) * 132 + col + 1] = acc[nt][3];
    }
    __syncthreads();
    int j = tid >> 1, t0 = (tid & 1) * 64;
    float bias = g_biasv[512 + j];
    float* ob = outp + ((size_t)b * 128 + j) * NSEQ + n0 + t0;
#pragma unroll
    for (int t = 0; t < 64; t += 4) {
        float4 v;
        v.x = res[(t0 + t + 0) * 132 + j] + bias;
        v.y = res[(t0 + t + 1) * 132 + j] + bias;
        v.z = res[(t0 + t + 2) * 132 + j] + bias;
        v.w = res[(t0 + t + 3) * 132 + j] + bias;
        *(float4*)(ob + t) = v;
    }
}

// ---------------- launch ----------------
extern "C" void kernel_launch(void* const* d_in, const int* in_sizes, int n_in,
                              void* d_out, int out_size) {
    const float* front  = (const float*)d_in[0];
    const float* back   = (const float*)d_in[1];
    const float* ln0w   = (const float*)d_in[2];
    const float* ln0b   = (const float*)d_in[3];
    const float* ln1w   = (const float*)d_in[4];
    const float* ln1b   = (const float*)d_in[5];
    const float* Wx     = (const float*)d_in[6];
    const float* Wz     = (const float*)d_in[7];
    const float* conv_w = (const float*)d_in[8];
    const float* conv_b = (const float*)d_in[9];
    const float* Wxproj = (const float*)d_in[10];
    const float* Wdt    = (const float*)d_in[11];
    const float* bdt    = (const float*)d_in[12];
    const float* A_log  = (const float*)d_in[13];
    const float* Dp     = (const float*)d_in[14];
    const float* Wout_m = (const float*)d_in[15];
    const float* bout_m = (const float*)d_in[16];
    const float* Wout   = (const float*)d_in[17];
    const float* bout   = (const float*)d_in[18];
    float* out = (float*)d_out;

    const int SM_MMA = 208896;
    cudaFuncSetAttribute(gemm_in_kernel, cudaFuncAttributeMaxDynamicSharedMemorySize, SM_MMA);
    cudaFuncSetAttribute(gemm_out_kernel, cudaFuncAttributeMaxDynamicSharedMemorySize, SM_MMA);

    prep_w_kernel<<<dim3(128, 7), 128>>>(ln0w, ln0b, ln1w, ln1b, Wx, Wz, Wout_m, bout_m, Wout, bout);
    gemm_in_kernel<<<dim3(NTILE, 2), 256, SM_MMA>>>(front, back, conv_w, conv_b, Wxproj);
    scan_a_kernel<<<2048, 128>>>(A_log, Wdt, bdt);
    scan_b1_kernel<<<256, 256>>>();
    scan_b2_kernel<<<32, 256>>>();
    scan_b3_kernel<<<256, 256>>>();
    scan_c_kernel<<<2048, 128>>>(A_log, Dp, Wdt, bdt);
    gemm_out_kernel<<<NTILE, 256, SM_MMA>>>(out, front, back);
}

// round 15
// speedup vs baseline: 1.3802x; 1.3802x over previous
#include <cuda_runtime.h>
#include <cuda_bf16.h>
#include <cuda_fp16.h>
#include <cstdint>

#define NSEQ   16384
#define BNTOK  65536
#define LC     64
#define NCH    256
#define NTILE  512
#define SASTR  272
#define R1OFF  69632u
#define R2OFF  139264u

__device__ __nv_bfloat16 g_ybf[2][2][(size_t)BNTOK * 128];
__device__ __nv_bfloat16 g_Wtb[7][2][16384];
__device__ float g_biasv[640];

__device__ __half g_z [2u*BNTOK*128];
__device__ __half g_uc[2u*BNTOK*128];
__device__ float g_xdbl[2u*BNTOK*24];
__device__ float g_P [2u*4*NCH*128*8];
__device__ float g_Q [2u*4*NCH*128*8];
__device__ float g_H [2u*4*NCH*128*8];
__device__ float g_segP[65536], g_segQ[65536], g_segH[65536];

__device__ __forceinline__ float sigmoidf_fast(float x) { return 1.0f / (1.0f + __expf(-x)); }
__device__ __forceinline__ float softplusf(float x) { return (x > 15.0f) ? x : __logf(1.0f + __expf(x)); }
__device__ __forceinline__ uint32_t su32(const void* p) { return (uint32_t)__cvta_generic_to_shared(p); }

__device__ __forceinline__ void cpa16(uint32_t s, const void* g) {
    asm volatile("cp.async.cg.shared.global [%0], [%1], 16;" :: "r"(s), "l"(g));
}
#define CP_COMMIT() asm volatile("cp.async.commit_group;")
#define CP_WAIT(n)  asm volatile("cp.async.wait_group %0;" :: "n"(n))

__device__ __forceinline__ void splt(float a, float b, uint32_t& hi, uint32_t& lo) {
    __nv_bfloat162 h, l;
    h.x = __float2bfloat16_rn(a); h.y = __float2bfloat16_rn(b);
    l.x = __float2bfloat16_rn(a - __bfloat162float(h.x));
    l.y = __float2bfloat16_rn(b - __bfloat162float(h.y));
    hi = *(uint32_t*)&h; lo = *(uint32_t*)&l;
}
__device__ __forceinline__ void ldsm4(uint32_t addr, uint32_t r[4]) {
    asm volatile("ldmatrix.sync.aligned.m8n8.x4.shared.b16 {%0,%1,%2,%3}, [%4];"
                 : "=r"(r[0]), "=r"(r[1]), "=r"(r[2]), "=r"(r[3]) : "r"(addr));
}
__device__ __forceinline__ void mma16816(float d[4], const uint32_t a[4], const uint32_t b[2]) {
    asm volatile("mma.sync.aligned.m16n8k16.row.col.f32.bf16.bf16.f32 "
                 "{%0,%1,%2,%3},{%4,%5,%6,%7},{%8,%9},{%0,%1,%2,%3};"
                 : "+f"(d[0]), "+f"(d[1]), "+f"(d[2]), "+f"(d[3])
                 : "r"(a[0]), "r"(a[1]), "r"(a[2]), "r"(a[3]), "r"(b[0]), "r"(b[1]));
}

__device__ __forceinline__ void cpa_plane(const __nv_bfloat16* __restrict__ g,
                                          uint32_t s, int tid) {
#pragma unroll
    for (int it = 0; it < 8; ++it) {
        int idx = tid + it * 256;
        int r = idx >> 4, c = idx & 15;
        cpa16(s + (uint32_t)(r * SASTR + c * 16), (const char*)g + idx * 16);
    }
}

__device__ __forceinline__ void gemm_compute(uint32_t Ab0, uint32_t Bb0, float acc[16][4],
                                             int warp, int lane) {
    int row = lane & 7, g = lane >> 3;
    uint32_t aoff = (uint32_t)((warp * 16 + (g & 1) * 8 + row) * SASTR + (g >> 1) * 16);
    uint32_t boff = (uint32_t)(((g >> 1) * 8 + row) * SASTR + (g & 1) * 16);
#pragma unroll
    for (int pass = 0; pass < 3; ++pass) {
        uint32_t Ab = Ab0 + (pass == 1 ? 34816u : 0u);
        uint32_t Bb = Bb0 + (pass == 2 ? 34816u : 0u);
#pragma unroll
        for (int kk = 0; kk < 8; ++kk) {
            uint32_t k2 = (uint32_t)kk * 32u;
            uint32_t a[4];
            ldsm4(Ab + aoff + k2, a);
#pragma unroll
            for (int nt = 0; nt < 8; ++nt) {
                uint32_t br[4];
                ldsm4(Bb + boff + (uint32_t)(nt * 16 * SASTR) + k2, br);
                mma16816(acc[2 * nt], a, br);
                mma16816(acc[2 * nt + 1], a, br + 2);
            }
        }
    }
}

// ---------------- prep_w ----------------
extern "C" __global__ void prep_w_kernel(
    const float* __restrict__ ln0w, const float* __restrict__ ln0b,
    const float* __restrict__ ln1w, const float* __restrict__ ln1b,
    const float* __restrict__ Wx, const float* __restrict__ Wz,
    const float* __restrict__ Wm, const float* __restrict__ bm,
    const float* __restrict__ Wout, const float* __restrict__ bout) {
    int j = blockIdx.x, pl = blockIdx.y, k = threadIdx.x;
    __shared__ float red[128];
    float v = 0.f, bc = 0.f;
    if (pl < 4) {
        int dir = pl >> 1;
        const float* W  = ((pl & 1) ? Wz : Wx) + dir * 16384;
        const float* lw = ((pl & 1) ? ln1w : ln0w) + dir * 128;
        const float* lb = ((pl & 1) ? ln1b : ln0b) + dir * 128;
        float wv = W[k * 128 + j];
        v = lw[k] * wv; bc = lb[k] * wv;
    } else if (pl == 4) {
        float wv = Wout[k * 128 + j];
        v = wv; bc = 0.5f * (bm[k] + bm[128 + k]) * wv;
    } else {
        int i = pl - 5;
        float acc = 0.f;
        for (int t = 0; t < 128; ++t) acc += Wm[i * 16384 + k * 128 + t] * Wout[t * 128 + j];
        v = 0.5f * acc;
    }
    __nv_bfloat16 h = __float2bfloat16_rn(v);
    g_Wtb[pl][0][j * 128 + k] = h;
    g_Wtb[pl][1][j * 128 + k] = __float2bfloat16_rn(v - __bfloat162float(h));
    if (pl < 5) {
        red[k] = bc; __syncthreads();
        if (k == 0) {
            float s = 0.f;
            for (int t = 0; t < 128; ++t) s += red[t];
            if (pl < 4) g_biasv[pl * 128 + j] = s;
            else        g_biasv[512 + j] = s + bout[j];
        }
    }
}

// ---------------- gemm_in ----------------
extern "C" __global__ void __launch_bounds__(256) gemm_in_kernel(
    const float* __restrict__ front, const float* __restrict__ back,
    const float* __restrict__ conv_w, const float* __restrict__ conv_b,
    const float* __restrict__ Wxproj) {
    extern __shared__ unsigned char smu[];
    __shared__ float s_biasu[128], s_biasz[128];
    __shared__ float s_uh[3 * 128];
    __shared__ float s_cw[128 * 4];
    __shared__ float s_cb[128];
    __shared__ float s_sum[2][128], s_sum2[2][128];
    __shared__ float s_mean[128], s_rstd[128];
    __shared__ float s_hx[3][128];
    __shared__ float s_hst[6];
    int tid = threadIdx.x, warp = tid >> 5, lane = tid & 31;
    int T = blockIdx.x, p = blockIdx.y;
    int ucm = p ? 2 : 0, zcm = p ? 1 : 3;
    int udir = p, zdir = 1 - p;
    int g0 = T * 128, b = g0 >> 14, n0 = g0 & (NSEQ - 1);
    const float* src = (p ? back : front) + (size_t)b * 128 * NSEQ + n0;
    uint32_t sb = su32(smu);

#pragma unroll
    for (int it = 0; it < 16; ++it) {
        int idx = tid + it * 256, d = idx >> 5, v = idx & 31;
        cpa16(sb + R1OFF + (uint32_t)(d * 528 + v * 16), src + (size_t)d * NSEQ + v * 4);
    }
    CP_COMMIT();
    cpa_plane(g_Wtb[zcm][0], sb + R2OFF, tid);
    cpa_plane(g_Wtb[zcm][1], sb + R2OFF + 34816u, tid);
    CP_COMMIT();
    if (tid < 128) {
        s_biasu[tid] = g_biasv[ucm * 128 + tid];
        s_biasz[tid] = g_biasv[zcm * 128 + tid];
        *(float4*)(s_cw + tid * 4) = *(const float4*)(conv_w + udir * 512 + tid * 4);
        s_cb[tid] = conv_b[udir * 128 + tid];
    }
    CP_WAIT(1);
    __syncthreads();

    float* xt = (float*)(smu + R1OFF);
    {
        int t = tid & 127, hf = tid >> 7;
        float a = 0.f, q = 0.f;
        for (int d = hf * 64; d < hf * 64 + 64; ++d) {
            float x = xt[d * 132 + t];
            a += x; q += x * x;
        }
        s_sum[hf][t] = a; s_sum2[hf][t] = q;
    }
    __syncthreads();
    if (tid < 128) {
        float m = (s_sum[0][tid] + s_sum[1][tid]) * (1.f / 128.f);
        float q = (s_sum2[0][tid] + s_sum2[1][tid]) * (1.f / 128.f);
        s_mean[tid] = m;
        s_rstd[tid] = rsqrtf(q - m * m + 1e-5f);
    }
    __syncthreads();
#pragma unroll
    for (int it = 0; it < 8; ++it) {
        int u = tid + it * 256;
        int tok = u & 127, kk = (u >> 7) * 8;
        float m = s_mean[tok], r = s_rstd[tok];
        float v[8];
#pragma unroll
        for (int q = 0; q < 8; ++q) v[q] = (xt[(kk + q) * 132 + tok] - m) * r;
        uint32_t hi[4], lo[4];
#pragma unroll
        for (int r2 = 0; r2 < 4; ++r2) splt(v[2 * r2], v[2 * r2 + 1], hi[r2], lo[r2]);
        *(uint4*)(smu + tok * SASTR + kk * 2)         = make_uint4(hi[0], hi[1], hi[2], hi[3]);
        *(uint4*)(smu + 34816 + tok * SASTR + kk * 2) = make_uint4(lo[0], lo[1], lo[2], lo[3]);
    }
    __syncthreads();
    cpa_plane(g_Wtb[ucm][0], sb + R1OFF, tid);
    cpa_plane(g_Wtb[ucm][1], sb + R1OFF + 34816u, tid);
    CP_COMMIT();
    CP_WAIT(1);
    __syncthreads();

    int r0 = warp * 16 + (lane >> 2);
    int cb2 = (lane & 3) * 2;
    float acc[16][4];

    // ---- z GEMM: A=R0, B=R2 ----
#pragma unroll
    for (int n = 0; n < 16; ++n)
#pragma unroll
        for (int q = 0; q < 4; ++q) acc[n][q] = 0.f;
    gemm_compute(sb, sb + R2OFF, acc, warp, lane);
    {
        __half* d0 = g_z + (size_t)zdir * BNTOK * 128 + ((size_t)(T * 128) + r0) * 128;
#pragma unroll
        for (int nt = 0; nt < 16; ++nt) {
            int col = nt * 8 + cb2;
            float b0 = s_biasz[col], b1 = s_biasz[col + 1];
            *(__half2*)(d0 + col)           = __floats2half2_rn(acc[nt][0] + b0, acc[nt][1] + b1);
            *(__half2*)(d0 + 8 * 128 + col) = __floats2half2_rn(acc[nt][2] + b0, acc[nt][3] + b1);
        }
    }
    CP_WAIT(0);
    __syncthreads();

    // ---- u GEMM: A=R0, B=R1 ----
#pragma unroll
    for (int n = 0; n < 16; ++n)
#pragma unroll
        for (int q = 0; q < 4; ++q) acc[n][q] = 0.f;
    gemm_compute(sb, sb + R1OFF, acc, warp, lane);

    __syncthreads();
    float* ut = (float*)(smu + R2OFF);
#pragma unroll
    for (int nt = 0; nt < 16; ++nt) {
        int col = nt * 8 + cb2;
        float b0 = s_biasu[col], b1 = s_biasu[col + 1];
        ut[r0 * 132 + col]           = acc[nt][0] + b0;
        ut[r0 * 132 + col + 1]       = acc[nt][1] + b1;
        ut[(r0 + 8) * 132 + col]     = acc[nt][2] + b0;
        ut[(r0 + 8) * 132 + col + 1] = acc[nt][3] + b1;
    }
    if (T & 127) {
        if (tid < 128) {
            const float* hs = (p ? back : front) + (size_t)b * 128 * NSEQ + (n0 - 3);
            s_hx[0][tid] = hs[(size_t)tid * NSEQ + 0];
            s_hx[1][tid] = hs[(size_t)tid * NSEQ + 1];
            s_hx[2][tid] = hs[(size_t)tid * NSEQ + 2];
        }
        __syncthreads();
        if (tid < 6) {
            int k = tid >> 1, sq = tid & 1;
            float s = 0.f;
            for (int d = 0; d < 128; ++d) {
                float x = s_hx[k][d];
                s += sq ? x * x : x;
            }
            s_hst[tid] = s;
        }
        __syncthreads();
        if (tid < 128) {
#pragma unroll
            for (int k = 0; k < 3; ++k) {
                float m = s_hst[2 * k] * (1.f / 128.f);
                float q = s_hst[2 * k + 1] * (1.f / 128.f);
                float r = rsqrtf(q - m * m + 1e-5f);
                s_hx[k][tid] = (s_hx[k][tid] - m) * r;
            }
        }
        __syncthreads();
        if (tid < 128) {
            int j = tid;
            const __nv_bfloat16* wh = (const __nv_bfloat16*)(smu + R1OFF + j * SASTR);
            const __nv_bfloat16* wl = (const __nv_bfloat16*)(smu + R1OFF + 34816 + j * SASTR);
            float a0 = s_biasu[j], a1 = s_biasu[j], a2 = s_biasu[j];
            for (int k = 0; k < 128; ++k) {
                float w = __bfloat162float(wh[k]) + __bfloat162float(wl[k]);
                a0 += w * s_hx[0][k];
                a1 += w * s_hx[1][k];
                a2 += w * s_hx[2][k];
            }
            s_uh[j] = a0; s_uh[128 + j] = a1; s_uh[256 + j] = a2;
        }
    } else {
        if (tid < 128) { s_uh[tid] = 0.f; s_uh[128 + tid] = 0.f; s_uh[256 + tid] = 0.f; }
    }
    __syncthreads();
    float* uct = (float*)smu;
    float* wxpd = (float*)(smu + R1OFF);
    __half* ucg = g_uc + (size_t)udir * BNTOK * 128 + (size_t)T * 128 * 128;
#pragma unroll
    for (int it = 0; it < 12; ++it)
        wxpd[tid + it * 256] = Wxproj[udir * 3072 + tid + it * 256];
#pragma unroll
    for (int it = 0; it < 16; ++it) {
        int idx = tid + it * 256;
        int t = idx >> 5, dq = (idx & 31) * 4;
        float4 r3, r2, r1, r0v;
        r0v = *(float4*)(ut + t * 132 + dq);
        if (t >= 3) {
            r3 = *(float4*)(ut + (t - 3) * 132 + dq);
            r2 = *(float4*)(ut + (t - 2) * 132 + dq);
            r1 = *(float4*)(ut + (t - 1) * 132 + dq);
        } else {
            r3 = (t < 3) ? *(float4*)(s_uh + t * 128 + dq)       : *(float4*)(ut + (t - 3) * 132 + dq);
            r2 = (t < 2) ? *(float4*)(s_uh + (t + 1) * 128 + dq) : *(float4*)(ut + (t - 2) * 132 + dq);
            r1 = (t < 1) ? *(float4*)(s_uh + (t + 2) * 128 + dq) : *(float4*)(ut + (t - 1) * 132 + dq);
        }
        float4 o;
        float* w;
        w = s_cw + (dq + 0) * 4;
        o.x = s_cb[dq + 0] + w[0] * r3.x + w[1] * r2.x + w[2] * r1.x + w[3] * r0v.x;
        w = s_cw + (dq + 1) * 4;
        o.y = s_cb[dq + 1] + w[0] * r3.y + w[1] * r2.y + w[2] * r1.y + w[3] * r0v.y;
        w = s_cw + (dq + 2) * 4;
        o.z = s_cb[dq + 2] + w[0] * r3.z + w[1] * r2.z + w[2] * r1.z + w[3] * r0v.z;
        w = s_cw + (dq + 3) * 4;
        o.w = s_cb[dq + 3] + w[0] * r3.w + w[1] * r2.w + w[2] * r1.w + w[3] * r0v.w;
        o.x *= sigmoidf_fast(o.x); o.y *= sigmoidf_fast(o.y);
        o.z *= sigmoidf_fast(o.z); o.w *= sigmoidf_fast(o.w);
        *(float4*)(uct + t * 132 + dq) = o;
        __half2 h01 = __floats2half2_rn(o.x, o.y);
        __half2 h23 = __floats2half2_rn(o.z, o.w);
        *(uint2*)(ucg + (size_t)t * 128 + dq) = make_uint2(*(uint32_t*)&h01, *(uint32_t*)&h23);
    }
    __syncthreads();
    {
        int tok = tid >> 1, hf = tid & 1;
        float a2[12];
#pragma unroll
        for (int q = 0; q < 12; ++q) a2[q] = 0.f;
        const float* ur = uct + tok * 132;
        const float* wp = wxpd + hf * 12;
        for (int d = 0; d < 128; ++d) {
            float uv = ur[d];
#pragma unroll
            for (int q = 0; q < 12; ++q) a2[q] += uv * wp[d * 24 + q];
        }
        float* xo = g_xdbl + ((size_t)udir * BNTOK + T * 128 + tok) * 24 + hf * 12;
        *(float4*)(xo + 0) = make_float4(a2[0], a2[1], a2[2], a2[3]);
        *(float4*)(xo + 4) = make_float4(a2[4], a2[5], a2[6], a2[7]);
        *(float4*)(xo + 8) = make_float4(a2[8], a2[9], a2[10], a2[11]);
    }
}

// ---------------- scan_a ----------------
extern "C" __global__ void __launch_bounds__(128) scan_a_kernel(
    const float* __restrict__ A_log, const float* __restrict__ Wdt,
    const float* __restrict__ bdt) {
    __shared__ float xds[LC * 24];
    __shared__ float wdts[8 * 128], bdts[128];
    int bx = blockIdx.x, c = bx & (NCH - 1), b = (bx >> 8) & 3, i = bx >> 10, d = threadIdx.x;
    float a[8];
#pragma unroll
    for (int s = 0; s < 8; ++s) a[s] = -__expf(A_log[i * 1024 + d * 8 + s]);
    bool st = true;
#pragma unroll
    for (int s = 1; s < 8; ++s)
        st = st && (fabsf(a[s] - (float)(s + 1) * a[0]) <= 1e-4f * fabsf(a[s]));
    size_t g0 = (size_t)i * BNTOK + b * NSEQ + c * LC;
#pragma unroll
    for (int k = 0; k < 12; ++k) xds[d + k * 128] = g_xdbl[g0 * 24 + d + k * 128];
#pragma unroll
    for (int k = 0; k < 8; ++k) wdts[d + k * 128] = Wdt[i * 1024 + d + k * 128];
    bdts[d] = bdt[i * 128 + d];
    __syncthreads();
    float P[8], h[8];
#pragma unroll
    for (int s = 0; s < 8; ++s) { P[s] = 1.f; h[s] = 0.f; }
    const __half* ucp = g_uc + g0 * 128 + d;
    if (st) {
        float a0 = a[0];
#pragma unroll 2
        for (int t = 0; t < LC; ++t) {
            float dtacc = bdts[d];
#pragma unroll
            for (int r = 0; r < 8; ++r) dtacc += xds[t * 24 + r] * wdts[r * 128 + d];
            float dtv = softplusf(dtacc);
            float du = dtv * __half2float(ucp[t * 128]);
            float e1 = __expf(dtv * a0);
            float dA = e1;
#pragma unroll
            for (int s = 0; s < 8; ++s) {
                P[s] *= dA;
                h[s] = dA * h[s] + du * xds[t * 24 + 8 + s];
                dA *= e1;
            }
        }
    } else {
#pragma unroll 2
        for (int t = 0; t < LC; ++t) {
            float dtacc = bdts[d];
#pragma unroll
            for (int r = 0; r < 8; ++r) dtacc += xds[t * 24 + r] * wdts[r * 128 + d];
            float dtv = softplusf(dtacc);
            float du = dtv * __half2float(ucp[t * 128]);
#pragma unroll
            for (int s = 0; s < 8; ++s) {
                float dA = __expf(dtv * a[s]);
                P[s] *= dA;
                h[s] = dA * h[s] + du * xds[t * 24 + 8 + s];
            }
        }
    }
    size_t o = ((size_t)((i * 4 + b) * NCH + c)) * 1024 + d * 8;
    *(float4*)(g_P + o) = make_float4(P[0], P[1], P[2], P[3]);
    *(float4*)(g_P + o + 4) = make_float4(P[4], P[5], P[6], P[7]);
    *(float4*)(g_Q + o) = make_float4(h[0], h[1], h[2], h[3]);
    *(float4*)(g_Q + o + 4) = make_float4(h[4], h[5], h[6], h[7]);
}

// ---------------- scan_b (tree) ----------------
extern "C" __global__ void __launch_bounds__(256) scan_b1_kernel() {
    int gid = blockIdx.x * 256 + threadIdx.x;
    int seg = gid >> 13, rem = gid & 8191;
    size_t base = (size_t)(rem >> 10) * NCH * 1024 + (size_t)(seg * 32) * 1024 + (rem & 1023);
    float Pa = 1.f, Qa = 0.f;
    for (int k0 = 0; k0 < 32; k0 += 8) {
        float P8[8], Q8[8];
#pragma unroll
        for (int k = 0; k < 8; ++k) {
            size_t o = base + (size_t)(k0 + k) * 1024;
            P8[k] = g_P[o]; Q8[k] = g_Q[o];
        }
#pragma unroll
        for (int k = 0; k < 8; ++k) { Qa = P8[k] * Qa + Q8[k]; Pa *= P8[k]; }
    }
    g_segP[seg * 8192 + rem] = Pa;
    g_segQ[seg * 8192 + rem] = Qa;
}
extern "C" __global__ void __launch_bounds__(256) scan_b2_kernel() {
    int gid = blockIdx.x * 256 + threadIdx.x;
    float Ps[8], Qs[8];
#pragma unroll
    for (int s = 0; s < 8; ++s) { Ps[s] = g_segP[s * 8192 + gid]; Qs[s] = g_segQ[s * 8192 + gid]; }
    float h = 0.f;
#pragma unroll
    for (int s = 0; s < 8; ++s) {
        g_segH[s * 8192 + gid] = h;
        h = Ps[s] * h + Qs[s];
    }
}
extern "C" __global__ void __launch_bounds__(256) scan_b3_kernel() {
    int gid = blockIdx.x * 256 + threadIdx.x;
    int seg = gid >> 13, rem = gid & 8191;
    size_t base = (size_t)(rem >> 10) * NCH * 1024 + (size_t)(seg * 32) * 1024 + (rem & 1023);
    float h = g_segH[seg * 8192 + rem];
    for (int k0 = 0; k0 < 32; k0 += 8) {
        float P8[8], Q8[8];
#pragma unroll
        for (int k = 0; k < 8; ++k) {
            size_t o = base + (size_t)(k0 + k) * 1024;
            P8[k] = g_P[o]; Q8[k] = g_Q[o];
        }
#pragma unroll
        for (int k = 0; k < 8; ++k) {
            size_t o = base + (size_t)(k0 + k) * 1024;
            g_H[o] = h;
            h = P8[k] * h + Q8[k];
        }
    }
}

// ---------------- scan_c ----------------
extern "C" __global__ void __launch_bounds__(128) scan_c_kernel(
    const float* __restrict__ A_log, const float* __restrict__ Dp,
    const float* __restrict__ Wdt, const float* __restrict__ bdt) {
    __shared__ float xds[LC * 24];
    __shared__ float wdts[8 * 128], bdts[128];
    __shared__ float ys_s[LC * 131];
    int bx = blockIdx.x, c = bx & (NCH - 1), b = (bx >> 8) & 3, i = bx >> 10, d = threadIdx.x;
    float a[8];
#pragma unroll
    for (int s = 0; s < 8; ++s) a[s] = -__expf(A_log[i * 1024 + d * 8 + s]);
    bool st = true;
#pragma unroll
    for (int s = 1; s < 8; ++s)
        st = st && (fabsf(a[s] - (float)(s + 1) * a[0]) <= 1e-4f * fabsf(a[s]));
    float dp = Dp[i * 128 + d];
    size_t g0 = (size_t)i * BNTOK + b * NSEQ + c * LC;
#pragma unroll
    for (int k = 0; k < 12; ++k) xds[d + k * 128] = g_xdbl[g0 * 24 + d + k * 128];
#pragma unroll
    for (int k = 0; k < 8; ++k) wdts[d + k * 128] = Wdt[i * 1024 + d + k * 128];
    bdts[d] = bdt[i * 128 + d];
    __syncthreads();
    size_t o = ((size_t)((i * 4 + b) * NCH + c)) * 1024 + d * 8;
    float h[8];
    float4 h0 = *(const float4*)(g_H + o), h1 = *(const float4*)(g_H + o + 4);
    h[0] = h0.x; h[1] = h0.y; h[2] = h0.z; h[3] = h0.w;
    h[4] = h1.x; h[5] = h1.y; h[6] = h1.z; h[7] = h1.w;
    const __half* ucp = g_uc + g0 * 128 + d;
    const __half* zp  = g_z  + g0 * 128 + d;
    if (st) {
        float a0 = a[0];
#pragma unroll 2
        for (int t = 0; t < LC; ++t) {
            float dtacc = bdts[d];
#pragma unroll
            for (int r = 0; r < 8; ++r) dtacc += xds[t * 24 + r] * wdts[r * 128 + d];
            float dtv = softplusf(dtacc);
            float ucv = __half2float(ucp[t * 128]), zv = __half2float(zp[t * 128]);
            float du = dtv * ucv, y = 0.f;
            float e1 = __expf(dtv * a0);
            float dA = e1;
#pragma unroll
            for (int s = 0; s < 8; ++s) {
                h[s] = dA * h[s] + du * xds[t * 24 + 8 + s];
                y += h[s] * xds[t * 24 + 16 + s];
                dA *= e1;
            }
            ys_s[t * 131 + d] = (y + dp * ucv) * (zv * sigmoidf_fast(zv));
        }
    } else {
#pragma unroll 2
        for (int t = 0; t < LC; ++t) {
            float dtacc = bdts[d];
#pragma unroll
            for (int r = 0; r < 8; ++r) dtacc += xds[t * 24 + r] * wdts[r * 128 + d];
            float dtv = softplusf(dtacc);
            float ucv = __half2float(ucp[t * 128]), zv = __half2float(zp[t * 128]);
            float du = dtv * ucv, y = 0.f;
#pragma unroll
            for (int s = 0; s < 8; ++s) {
                float dA = __expf(dtv * a[s]);
                h[s] = dA * h[s] + du * xds[t * 24 + 8 + s];
                y += h[s] * xds[t * 24 + 16 + s];
            }
            ys_s[t * 131 + d] = (y + dp * ucv) * (zv * sigmoidf_fast(zv));
        }
    }
    __syncthreads();
    int tile = (b * NSEQ + c * LC) >> 7;
    int half = (c & 1) * 64;
#pragma unroll
    for (int it = 0; it < 8; ++it) {
        int u = d + it * 128;
        int tt = u & 63, kk = (u >> 6) * 8;
        uint32_t hi[4], lo[4];
#pragma unroll
        for (int r = 0; r < 4; ++r)
            splt(ys_s[tt * 131 + kk + 2 * r], ys_s[tt * 131 + kk + 2 * r + 1], hi[r], lo[r]);
        size_t off = ((size_t)(tile * 128 + half + tt)) * 128 + kk;
        *(uint4*)(&g_ybf[i][0][off]) = make_uint4(hi[0], hi[1], hi[2], hi[3]);
        *(uint4*)(&g_ybf[i][1][off]) = make_uint4(lo[0], lo[1], lo[2], lo[3]);
    }
}

// ---------------- gemm_out ----------------
extern "C" __global__ void __launch_bounds__(256) gemm_out_kernel(
    float* __restrict__ outp, const float* __restrict__ front,
    const float* __restrict__ back) {
    extern __shared__ unsigned char smu[];
    int tid = threadIdx.x, warp = tid >> 5, lane = tid & 31;
    int T = blockIdx.x, g0 = T * 128, b = g0 >> 14, n0 = g0 & (NSEQ - 1);
    uint32_t sb = su32(smu);
    float acc[16][4];
#pragma unroll
    for (int n = 0; n < 16; ++n)
#pragma unroll
        for (int q = 0; q < 4; ++q) acc[n][q] = 0.f;
    size_t abase = (size_t)T * 128 * 128;

    cpa_plane(&g_ybf[0][0][abase], sb + R2OFF, tid);
    cpa_plane(&g_ybf[0][1][abase], sb + R2OFF + 34816u, tid);
    CP_COMMIT();

    for (int r = 0; r < 2; ++r) {
        float* fm = (float*)(smu + R1OFF);
        float* bm = fm + 128 * 68;
        const float* fp = front + (size_t)b * 128 * NSEQ + n0 + r * 64;
        const float* bp = back  + (size_t)b * 128 * NSEQ + n0 + r * 64;
#pragma unroll
        for (int it = 0; it < 8; ++it) {
            int idx = tid + it * 256, d = idx >> 4, v = idx & 15;
            *(float4*)(fm + d * 68 + v * 4) = *(const float4*)(fp + (size_t)d * NSEQ + v * 4);
            *(float4*)(bm + d * 68 + v * 4) = *(const float4*)(bp + (size_t)d * NSEQ + v * 4);
        }
        __syncthreads();
#pragma unroll
        for (int it = 0; it < 4; ++it) {
            int u = tid + it * 256;
            int tok = u & 63, kk = (u >> 6) * 8;
            float v[8];
#pragma unroll
            for (int q = 0; q < 8; ++q)
                v[q] = 0.5f * (fm[(kk + q) * 68 + tok] + bm[(kk + q) * 68 + tok]);
            uint32_t hi[4], lo[4];
#pragma unroll
            for (int r2 = 0; r2 < 4; ++r2) splt(v[2 * r2], v[2 * r2 + 1], hi[r2], lo[r2]);
            *(uint4*)(smu + (r * 64 + tok) * SASTR + kk * 2)         = make_uint4(hi[0], hi[1], hi[2], hi[3]);
            *(uint4*)(smu + 34816 + (r * 64 + tok) * SASTR + kk * 2) = make_uint4(lo[0], lo[1], lo[2], lo[3]);
        }
        __syncthreads();
    }
    cpa_plane(g_Wtb[4][0], sb + R1OFF, tid);
    cpa_plane(g_Wtb[4][1], sb + R1OFF + 34816u, tid);
    CP_COMMIT();
    CP_WAIT(0);
    __syncthreads();
    gemm_compute(sb, sb + R1OFF, acc, warp, lane);
    __syncthreads();

    cpa_plane(g_Wtb[5][0], sb + R1OFF, tid);
    cpa_plane(g_Wtb[5][1], sb + R1OFF + 34816u, tid);
    CP_COMMIT();
    cpa_plane(&g_ybf[1][0][abase], sb, tid);
    cpa_plane(&g_ybf[1][1][abase], sb + 34816u, tid);
    CP_COMMIT();
    CP_WAIT(1);
    __syncthreads();
    gemm_compute(sb + R2OFF, sb + R1OFF, acc, warp, lane);
    __syncthreads();

    cpa_plane(g_Wtb[6][0], sb + R1OFF, tid);
    cpa_plane(g_Wtb[6][1], sb + R1OFF + 34816u, tid);
    CP_COMMIT();
    CP_WAIT(0);
    __syncthreads();
    gemm_compute(sb, sb + R1OFF, acc, warp, lane);

    __syncthreads();
    float* res = (float*)smu;
    int r0 = warp * 16 + (lane >> 2);
    int cb = (lane & 3) * 2;
#pragma unroll
    for (int nt = 0; nt < 16; ++nt) {
        int col = nt * 8 + cb;
        res[r0 * 132 + col]           = acc[nt][0];
        res[r0 * 132 + col + 1]       = acc[nt][1];
        res[(r0 + 8) * 132 + col]     = acc[nt][2];
        res[(r0 + 8) * 132 + col + 1] = acc[nt][3];
    }
    __syncthreads();
    int j = tid >> 1, t0 = (tid & 1) * 64;
    float bias = g_biasv[512 + j];
    float* ob = outp + ((size_t)b * 128 + j) * NSEQ + n0 + t0;
#pragma unroll
    for (int t = 0; t < 64; t += 4) {
        float4 v;
        v.x = res[(t0 + t + 0) * 132 + j] + bias;
        v.y = res[(t0 + t + 1) * 132 + j] + bias;
        v.z = res[(t0 + t + 2) * 132 + j] + bias;
        v.w = res[(t0 + t + 3) * 132 + j] + bias;
        *(float4*)(ob + t) = v;
    }
}

// ---------------- launch ----------------
extern "C" void kernel_launch(void* const* d_in, const int* in_sizes, int n_in,
                              void* d_out, int out_size) {
    const float* front  = (const float*)d_in[0];
    const float* back   = (const float*)d_in[1];
    const float* ln0w   = (const float*)d_in[2];
    const float* ln0b   = (const float*)d_in[3];
    const float* ln1w   = (const float*)d_in[4];
    const float* ln1b   = (const float*)d_in[5];
    const float* Wx     = (const float*)d_in[6];
    const float* Wz     = (const float*)d_in[7];
    const float* conv_w = (const float*)d_in[8];
    const float* conv_b = (const float*)d_in[9];
    const float* Wxproj = (const float*)d_in[10];
    const float* Wdt    = (const float*)d_in[11];
    const float* bdt    = (const float*)d_in[12];
    const float* A_log  = (const float*)d_in[13];
    const float* Dp     = (const float*)d_in[14];
    const float* Wout_m = (const float*)d_in[15];
    const float* bout_m = (const float*)d_in[16];
    const float* Wout   = (const float*)d_in[17];
    const float* bout   = (const float*)d_in[18];
    float* out = (float*)d_out;

    const int SM_MMA = 208896;
    cudaFuncSetAttribute(gemm_in_kernel, cudaFuncAttributeMaxDynamicSharedMemorySize, SM_MMA);
    cudaFuncSetAttribute(gemm_out_kernel, cudaFuncAttributeMaxDynamicSharedMemorySize, SM_MMA);

    prep_w_kernel<<<dim3(128, 7), 128>>>(ln0w, ln0b, ln1w, ln1b, Wx, Wz, Wout_m, bout_m, Wout, bout);
    gemm_in_kernel<<<dim3(NTILE, 2), 256, SM_MMA>>>(front, back, conv_w, conv_b, Wxproj);
    scan_a_kernel<<<2048, 128>>>(A_log, Wdt, bdt);
    scan_b1_kernel<<<256, 256>>>();
    scan_b2_kernel<<<32, 256>>>();
    scan_b3_kernel<<<256, 256>>>();
    scan_c_kernel<<<2048, 128>>>(A_log, Dp, Wdt, bdt);
    gemm_out_kernel<<<NTILE, 256, SM_MMA>>>(out, front, back);
}